// round 10
// baseline (speedup 1.0000x reference)
#include <cuda_runtime.h>
#include <cuda_fp16.h>
#include <cstdint>

#define T_STEPS 512
#define BATCH   512
#define FEAT    128
#define HID     512
#define TAGS    2
#define NG      2048          // 4*HID
#define K1      640           // FEAT + HID
#define K2      1024          // HID + HID
#define NCTA    128
#define MT      128
#define NT      64
#define NTHREADS 256          // 8 warps, warp tile 16x64
#define NTGROUP 32            // CTAs per M-group

// resident weights: per k64 block = 64 rows(N) x 128B = 8192 B
#define W1_BLKS 10
#define W2_BLKS 16
#define SM_W1   0
#define SM_W2   (W1_BLKS * 8192)                  // 81920
#define SM_AST  ((W1_BLKS + W2_BLKS) * 8192)      // 212992: per-warp A stages
#define SMEM_BYTES (SM_AST + 8 * 2048)            // 229376 (224KB)

// ------------------------- device globals (scratch) -------------------------
__device__ __half g_Wp1h[NG * K1];       // permuted [n][k], fp16
__device__ __half g_Wp2h[NG * K2];
__device__ float  g_b1[NG];
__device__ float  g_b2[NG];
__device__ __half g_sigh[T_STEPS * BATCH * FEAT];
__device__ __half g_h1[2][BATCH * HID];
__device__ __half g_h2[2][BATCH * HID];
__device__ float  g_c1[BATCH * HID];
__device__ float  g_c2[BATCH * HID];
__device__ unsigned g_bar4[4];
__device__ unsigned g_gen4[4];

// ------------------------------- helpers ------------------------------------
__device__ __forceinline__ float sigm(float x) { return 1.0f / (1.0f + __expf(-x)); }
__device__ __forceinline__ void cp16(uint32_t dst, const void* src) {
    asm volatile("cp.async.cg.shared.global [%0], [%1], 16;\n" :: "r"(dst), "l"(src));
}
#define CPA_COMMIT() asm volatile("cp.async.commit_group;\n")
#define CPA_WAIT0()  asm volatile("cp.async.wait_group 0;\n")
#define LDSM4(r0, r1, r2, r3, addr)                                            \
    asm volatile("ldmatrix.sync.aligned.m8n8.x4.shared.b16 {%0,%1,%2,%3}, [%4];" \
        : "=r"(r0), "=r"(r1), "=r"(r2), "=r"(r3) : "r"(addr))

__device__ __forceinline__ unsigned ld_acq(const unsigned* p) {
    unsigned v;
    asm volatile("ld.acquire.gpu.u32 %0, [%1];" : "=r"(v) : "l"(p) : "memory");
    return v;
}

// permuted column index n -> original gate row (gate-interleave of 16)
__device__ __forceinline__ int orig_row(long n) {
    int chunk = (int)(n >> 6), w = (int)(n & 63);
    int q = w >> 4, r = w & 15;
    return q * HID + chunk * 16 + r;
}

// ------------------------------ prep kernel ---------------------------------
__global__ void prep_kernel(const float* __restrict__ signal,
                            const float* __restrict__ Wih1, const float* __restrict__ Whh1,
                            const float* __restrict__ bih1, const float* __restrict__ bhh1,
                            const float* __restrict__ Wih2, const float* __restrict__ Whh2,
                            const float* __restrict__ bih2, const float* __restrict__ bhh2) {
    const long NW1 = (long)NG * K1;
    const long NW2 = (long)NG * K2;
    const long NSIG = (long)T_STEPS * BATCH * FEAT;
    const long NH   = (long)BATCH * HID;
    const long TOT = NW1 + NW2 + 2L * NG + NSIG + 6L * NH;
    for (long i = blockIdx.x * (long)blockDim.x + threadIdx.x; i < TOT;
         i += (long)gridDim.x * blockDim.x) {
        if (i < NW1) {
            long n = i / K1, k = i % K1;
            int o = orig_row(n);
            float v = (k < FEAT) ? Wih1[(long)o * FEAT + k]
                                 : Whh1[(long)o * HID + (k - FEAT)];
            g_Wp1h[i] = __float2half_rn(v);
        } else if (i < NW1 + NW2) {
            long j = i - NW1;
            long n = j / K2, k = j % K2;
            int o = orig_row(n);
            float v = (k < HID) ? Wih2[(long)o * HID + k]
                                : Whh2[(long)o * HID + (k - HID)];
            g_Wp2h[j] = __float2half_rn(v);
        } else if (i < NW1 + NW2 + NG) {
            long n = i - NW1 - NW2;
            int o = orig_row(n);
            g_b1[n] = bih1[o] + bhh1[o];
        } else if (i < NW1 + NW2 + 2L * NG) {
            long n = i - NW1 - NW2 - NG;
            int o = orig_row(n);
            g_b2[n] = bih2[o] + bhh2[o];
        } else if (i < NW1 + NW2 + 2L * NG + NSIG) {
            long j = i - NW1 - NW2 - 2L * NG;
            g_sigh[j] = __float2half_rn(signal[j]);
        } else {
            long j = i - (NW1 + NW2 + 2L * NG + NSIG);
            long seg = j / NH, o = j % NH;
            if      (seg == 0) g_h1[0][o] = __float2half_rn(0.f);
            else if (seg == 1) g_h1[1][o] = __float2half_rn(0.f);
            else if (seg == 2) g_h2[0][o] = __float2half_rn(0.f);
            else if (seg == 3) g_h2[1][o] = __float2half_rn(0.f);
            else if (seg == 4) g_c1[o]    = 0.f;
            else               g_c2[o]    = 0.f;
        }
    }
    if (blockIdx.x == 0 && threadIdx.x < 4) {
        g_bar4[threadIdx.x] = 0u;
        g_gen4[threadIdx.x] = 0u;
    }
}

// --------------------- per-M-group barrier (32 CTAs) -------------------------
__device__ __forceinline__ void group_sync(int mt, unsigned target) {
    __syncthreads();
    if (threadIdx.x == 0) {
        __threadfence();
        unsigned a = atomicAdd(&g_bar4[mt], 1u);
        if (a == NTGROUP - 1u) {
            atomicExch(&g_bar4[mt], 0u);
            __threadfence();
            atomicAdd(&g_gen4[mt], 1u);
        } else {
            while (ld_acq(&g_gen4[mt]) < target) { }
        }
        __threadfence();
    }
    __syncthreads();
}

// --------------------------- A prefetch (registers) --------------------------
struct Src {
    const __half* a0; int lda0; int split;   // k32 sub-chunk idx < split -> a0
    const __half* a1; int lda1;              // otherwise a1
};

__device__ __forceinline__ void pre(uint4 r[2], const Src& s, int idx,
                                    int rowA, int coff) {
    const __half* p;
    if (idx < s.split) p = s.a0 + (size_t)rowA * s.lda0 + idx * 32 + coff;
    else               p = s.a1 + (size_t)rowA * s.lda1 + (idx - s.split) * 32 + coff;
    r[0] = __ldcg((const uint4*)p);
    r[1] = __ldcg((const uint4*)(p + 8));
}

// ---------------------- sub-chunk MMA (B resident in smem) -------------------
__device__ __forceinline__ void mma_sub(uint32_t stg, const uint32_t a_off[2],
                                        uint32_t wphase, int k16g,
                                        const uint32_t bo_sw[4][4], float acc[8][4]) {
    #pragma unroll
    for (int kk = 0; kk < 2; kk++) {
        unsigned a0, a1, a2, a3;
        LDSM4(a0, a1, a2, a3, stg + a_off[kk]);
        const int kg = k16g + kk;
        const uint32_t wblk = wphase + (uint32_t)(kg >> 2) * 8192u;
        const int k4 = kg & 3;
        unsigned b[4][4];
        #pragma unroll
        for (int p = 0; p < 4; p++)
            LDSM4(b[p][0], b[p][1], b[p][2], b[p][3], wblk + bo_sw[p][k4]);
        #pragma unroll
        for (int ni = 0; ni < 8; ni++) {
            const int p = ni >> 1, hi = (ni & 1) * 2;
            asm volatile(
                "mma.sync.aligned.m16n8k16.row.col.f32.f16.f16.f32 "
                "{%0,%1,%2,%3}, {%4,%5,%6,%7}, {%8,%9}, {%0,%1,%2,%3};\n"
                : "+f"(acc[ni][0]), "+f"(acc[ni][1]),
                  "+f"(acc[ni][2]), "+f"(acc[ni][3])
                : "r"(a0), "r"(a1), "r"(a2), "r"(a3),
                  "r"(b[p][hi]), "r"(b[p][hi + 1]));
        }
    }
}

__device__ __forceinline__ void zero_acc(float acc[8][4]) {
    #pragma unroll
    for (int ni = 0; ni < 8; ni++)
        #pragma unroll
        for (int r = 0; r < 4; r++) acc[ni][r] = 0.f;
}

// ------------------- register-local LSTM epilogue ----------------------------
__device__ __forceinline__ void epilogue(const float acc[8][4],
                                         const float br[4][2][2],
                                         float* __restrict__ cbuf,
                                         __half* __restrict__ hout,
                                         int m0, int H0, int w, int lane) {
    const int r0 = m0 + w * 16 + (lane >> 2);
    #pragma unroll
    for (int rp = 0; rp < 2; rp++) {
        const int row = r0 + rp * 8;
        #pragma unroll
        for (int j = 0; j < 2; j++) {
            const int colb = H0 + j * 8 + 2 * (lane & 3);
            float2 c2 = *(float2*)(cbuf + (size_t)row * HID + colb);
            float hv[2];
            #pragma unroll
            for (int b = 0; b < 2; b++) {
                const int rg = rp * 2 + b;
                float gi = acc[0 + j][rg] + br[0][j][b];
                float gf = acc[2 + j][rg] + br[1][j][b];
                float gg = acc[4 + j][rg] + br[2][j][b];
                float go = acc[6 + j][rg] + br[3][j][b];
                float c  = b ? c2.y : c2.x;
                float cn = sigm(gf) * c + sigm(gi) * tanhf(gg);
                if (b) c2.y = cn; else c2.x = cn;
                hv[b] = sigm(go) * tanhf(cn);
            }
            *(float2*)(cbuf + (size_t)row * HID + colb) = c2;
            *(__half2*)(hout + (size_t)row * HID + colb) =
                __floats2half2_rn(hv[0], hv[1]);
        }
    }
}

// ----------------------------- output projection -----------------------------
__device__ __forceinline__ void out_calc(int tp, const __half* __restrict__ h2cur,
                                         const float* __restrict__ Wlin,
                                         const float* __restrict__ blin,
                                         float* __restrict__ out, int ct) {
    const int tid = threadIdx.x, lane = tid & 31, wid = tid >> 5;
    if (wid >= 4) return;
    const int b = ct * 4 + wid;
    const __half* hrow = h2cur + (size_t)b * HID;
    float s0 = 0.f, s1 = 0.f;
    #pragma unroll 8
    for (int k = lane; k < HID; k += 32) {
        float hv = __half2float(__ldcg(hrow + k));
        s0 += hv * __ldg(Wlin + k);
        s1 += hv * __ldg(Wlin + HID + k);
    }
    #pragma unroll
    for (int o = 16; o; o >>= 1) {
        s0 += __shfl_xor_sync(0xffffffffu, s0, o);
        s1 += __shfl_xor_sync(0xffffffffu, s1, o);
    }
    if (lane == 0) {
        out[(size_t)b * (T_STEPS * TAGS) + tp * TAGS + 0] = s0 + blin[0];
        out[(size_t)b * (T_STEPS * TAGS) + tp * TAGS + 1] = s1 + blin[1];
    }
}

// ------------------------------ persistent kernel ----------------------------
__global__ void __launch_bounds__(NTHREADS, 1)
lstm_persistent(const float* __restrict__ Wlin, const float* __restrict__ blin,
                float* __restrict__ out) {
    extern __shared__ char smc[];
    const uint32_t smu = (uint32_t)__cvta_generic_to_shared(smc);
    const int tid = threadIdx.x, w = tid >> 5, lane = tid & 31;
    const int ct = blockIdx.x;
    const int mt = ct >> 5, nt = ct & 31;    // 4 M-groups x 32 N-tiles
    const int m0 = mt * MT, n0 = nt * NT, H0 = nt * 16;

    // ---- preload resident W1 (10 blocks) + W2 (16 blocks) into smem ----
    {
        int row = tid >> 2, part = tid & 3;
        uint32_t rb = (uint32_t)(row * 128 + part * 32);
        uint32_t o0 = rb;        o0 ^= (o0 >> 3) & 0x70u;
        uint32_t o1 = rb + 16;   o1 ^= (o1 >> 3) & 0x70u;
        const __half* s1 = g_Wp1h + (size_t)(n0 + row) * K1 + part * 16;
        for (int ckk = 0; ckk < W1_BLKS; ckk++) {
            cp16(smu + SM_W1 + ckk * 8192 + o0, s1 + ckk * 64);
            cp16(smu + SM_W1 + ckk * 8192 + o1, s1 + ckk * 64 + 8);
        }
        const __half* s2 = g_Wp2h + (size_t)(n0 + row) * K2 + part * 16;
        for (int ckk = 0; ckk < W2_BLKS; ckk++) {
            cp16(smu + SM_W2 + ckk * 8192 + o0, s2 + ckk * 64);
            cp16(smu + SM_W2 + ckk * 8192 + o1, s2 + ckk * 64 + 8);
        }
        CPA_COMMIT();
        CPA_WAIT0();
        __syncthreads();
    }

    // ---- per-thread biases in registers ----
    float b1r[4][2][2], b2r[4][2][2];
    #pragma unroll
    for (int g = 0; g < 4; g++)
        #pragma unroll
        for (int j = 0; j < 2; j++)
            #pragma unroll
            for (int b = 0; b < 2; b++) {
                int c = n0 + g * 16 + j * 8 + 2 * (lane & 3) + b;
                b1r[g][j][b] = g_b1[c];
                b2r[g][j][b] = g_b2[c];
            }

    // ---- precomputed swizzled LDSM offsets for B (n16-block p, k16-in-block) ----
    const uint32_t b_off0 = (uint32_t)(((((lane >> 4) & 1) * 8 + (lane & 7)) * 128)
                                       + ((lane >> 3) & 1) * 16);
    uint32_t bo_sw[4][4];
    #pragma unroll
    for (int p = 0; p < 4; p++)
        #pragma unroll
        for (int kk = 0; kk < 4; kk++) {
            uint32_t bo = b_off0 + (uint32_t)(p * 2048 + kk * 32);
            bo ^= (bo >> 3) & 0x70u;
            bo_sw[p][kk] = bo;
        }

    // ---- per-warp A stage: 2 slots x 1KB; 2 rows packed per 128B line -------
    const uint32_t awbase = smu + SM_AST + (uint32_t)w * 2048u;
    char* const   awgen   = smc + SM_AST + (size_t)w * 2048u;
    const uint32_t wpre = (uint32_t)((lane >> 2) * 128 + ((lane >> 1) & 1) * 64
                                     + (lane & 1) * 32);
    const uint32_t wsw  = ((uint32_t)(lane >> 2) & 7u) << 4;
    const uint32_t wd0  = wpre ^ wsw;
    const uint32_t wd1  = (wpre + 16) ^ wsw;
    const int coff = (lane & 1) * 16;                 // halves
    const int rowA = m0 + w * 16 + (lane >> 1);
    const int rr = lane & 15;
    const uint32_t apre = (uint32_t)((rr >> 1) * 128 + (rr & 1) * 64 + (lane >> 4) * 16);
    const uint32_t asw  = ((uint32_t)(rr >> 1) & 7u) << 4;
    const uint32_t a_off[2] = { apre ^ asw, (apre + 32) ^ asw };

    float acc[8][4];
    uint4 rbuf[4][2];                         // depth-4 register prefetch ring
    unsigned round = 0;

    Src sa;                                   // phase A source (k32 units)
    sa.a0 = g_sigh;  sa.lda0 = FEAT; sa.split = FEAT / 32;   // 4
    sa.a1 = g_h1[0]; sa.lda1 = HID;
    #pragma unroll
    for (int d = 0; d < 4; d++) pre(rbuf[d], sa, d, rowA, coff);   // x_0 chunks 0..3

    for (int t = 0; t < T_STEPS; t++) {
        const int rb = t & 1, wb = rb ^ 1;
        if (t > 0) out_calc(t - 1, g_h2[rb], Wlin, blin, out, ct);

        // ---- phase A: gates1 = [x_t, h1] @ W1p^T  (20 k32 sub-chunks) ----
        sa.a1 = g_h1[rb];
        zero_acc(acc);
        #pragma unroll 4
        for (int j = 0; j < 20; j++) {
            char* slot = awgen + (j & 1) * 1024;
            *(uint4*)(slot + wd0) = rbuf[j & 3][0];
            *(uint4*)(slot + wd1) = rbuf[j & 3][1];
            __syncwarp();
            if (j + 4 < 20) pre(rbuf[j & 3], sa, j + 4, rowA, coff);
            mma_sub(awbase + (uint32_t)(j & 1) * 1024u, a_off,
                    smu + SM_W1, j * 2, bo_sw, acc);
        }
        epilogue(acc, b1r, g_c1, g_h1[wb], m0, H0, w, lane);

        // prefetch phase B sub-chunks idx 16..19 (h2[rb] half — stable pre-sync)
        Src sb;
        sb.a0 = g_h1[wb]; sb.lda0 = HID; sb.split = HID / 32;  // 16
        sb.a1 = g_h2[rb]; sb.lda1 = HID;
        #pragma unroll
        for (int d = 0; d < 4; d++) pre(rbuf[d], sb, 16 + d, rowA, coff);
        group_sync(mt, ++round);

        // ---- phase B: gates2 = [h1', h2] @ W2p^T  (32 k32, h2 half first) ----
        zero_acc(acc);
        #pragma unroll 4
        for (int j = 0; j < 32; j++) {
            char* slot = awgen + (j & 1) * 1024;
            *(uint4*)(slot + wd0) = rbuf[j & 3][0];
            *(uint4*)(slot + wd1) = rbuf[j & 3][1];
            __syncwarp();
            if (j + 4 < 32) pre(rbuf[j & 3], sb, (20 + j) & 31, rowA, coff);
            mma_sub(awbase + (uint32_t)(j & 1) * 1024u, a_off,
                    smu + SM_W2, ((16 + j) & 31) * 2, bo_sw, acc);
        }
        epilogue(acc, b2r, g_c2, g_h2[wb], m0, H0, w, lane);

        // prefetch next step's phase A sub-chunks 0..3 (x_{t+1} — dep-free)
        const int tn = (t + 1 < T_STEPS) ? t + 1 : t;
        sa.a0 = g_sigh + (size_t)tn * BATCH * FEAT;
        #pragma unroll
        for (int d = 0; d < 4; d++) pre(rbuf[d], sa, d, rowA, coff);
        group_sync(mt, ++round);
    }
    out_calc(T_STEPS - 1, g_h2[T_STEPS & 1], Wlin, blin, out, ct);
}

// --------------------------------- launcher ----------------------------------
extern "C" void kernel_launch(void* const* d_in, const int* in_sizes, int n_in,
                              void* d_out, int out_size) {
    const float* signal = (const float*)d_in[0];
    const float* Wih1   = (const float*)d_in[1];
    const float* Whh1   = (const float*)d_in[2];
    const float* bih1   = (const float*)d_in[3];
    const float* bhh1   = (const float*)d_in[4];
    const float* Wih2   = (const float*)d_in[5];
    const float* Whh2   = (const float*)d_in[6];
    const float* bih2   = (const float*)d_in[7];
    const float* bhh2   = (const float*)d_in[8];
    const float* Wlin   = (const float*)d_in[9];
    const float* blin   = (const float*)d_in[10];
    float* out = (float*)d_out;

    (void)in_sizes; (void)n_in; (void)out_size;

    cudaFuncSetAttribute(lstm_persistent,
                         cudaFuncAttributeMaxDynamicSharedMemorySize, SMEM_BYTES);

    prep_kernel<<<4096, 256>>>(signal, Wih1, Whh1, bih1, bhh1,
                               Wih2, Whh2, bih2, bhh2);
    lstm_persistent<<<NCTA, NTHREADS, SMEM_BYTES>>>(Wlin, blin, out);
}

// round 11
// speedup vs baseline: 1.4277x; 1.4277x over previous
#include <cuda_runtime.h>
#include <cuda_fp16.h>
#include <cstdint>

#define T_STEPS 512
#define BATCH   512
#define FEAT    128
#define HID     512
#define TAGS    2
#define NG      2048          // 4*HID
#define K1      640           // FEAT + HID
#define K2      1024          // HID + HID
#define NCTA    128
#define MT      128
#define NT      64
#define NTHREADS 256          // 8 warps, warp tile 16x64
#define NTGROUP 32            // CTAs per M-group

// resident weights: per k64 block = 64 rows(N) x 128B = 8192 B
#define W1_BLKS 10
#define W2_BLKS 16
#define SM_W1   0
#define SM_W2   (W1_BLKS * 8192)                  // 81920
#define SM_AST  ((W1_BLKS + W2_BLKS) * 8192)      // 212992: per-warp A stages
#define SMEM_BYTES (SM_AST + 8 * 2048)            // 229376 (224KB)

// ------------------------- device globals (scratch) -------------------------
__device__ __half g_Wp1h[NG * K1];       // permuted [n][k], fp16
__device__ __half g_Wp2h[NG * K2];
__device__ float  g_b1[NG];
__device__ float  g_b2[NG];
__device__ __half g_sigh[T_STEPS * BATCH * FEAT];
__device__ __half g_h1[2][BATCH * HID];
__device__ __half g_h2[2][BATCH * HID];
__device__ float  g_c1[BATCH * HID];
__device__ float  g_c2[BATCH * HID];
__device__ unsigned g_bar4[4];
__device__ unsigned g_gen4[4];

// ------------------------------- helpers ------------------------------------
__device__ __forceinline__ float sigm(float x) { return 1.0f / (1.0f + __expf(-x)); }
__device__ __forceinline__ void cp16(uint32_t dst, const void* src) {
    asm volatile("cp.async.cg.shared.global [%0], [%1], 16;\n" :: "r"(dst), "l"(src));
}
#define CPA_COMMIT() asm volatile("cp.async.commit_group;\n")
#define CPA_WAIT1()  asm volatile("cp.async.wait_group 1;\n")
#define CPA_WAIT0()  asm volatile("cp.async.wait_group 0;\n")
#define LDSM4(r0, r1, r2, r3, addr)                                            \
    asm volatile("ldmatrix.sync.aligned.m8n8.x4.shared.b16 {%0,%1,%2,%3}, [%4];" \
        : "=r"(r0), "=r"(r1), "=r"(r2), "=r"(r3) : "r"(addr))

__device__ __forceinline__ unsigned ld_acq(const unsigned* p) {
    unsigned v;
    asm volatile("ld.acquire.gpu.u32 %0, [%1];" : "=r"(v) : "l"(p) : "memory");
    return v;
}

// permuted column index n -> original gate row (gate-interleave of 16)
__device__ __forceinline__ int orig_row(long n) {
    int chunk = (int)(n >> 6), w = (int)(n & 63);
    int q = w >> 4, r = w & 15;
    return q * HID + chunk * 16 + r;
}

// ------------------------------ prep kernel ---------------------------------
__global__ void prep_kernel(const float* __restrict__ signal,
                            const float* __restrict__ Wih1, const float* __restrict__ Whh1,
                            const float* __restrict__ bih1, const float* __restrict__ bhh1,
                            const float* __restrict__ Wih2, const float* __restrict__ Whh2,
                            const float* __restrict__ bih2, const float* __restrict__ bhh2) {
    const long NW1 = (long)NG * K1;
    const long NW2 = (long)NG * K2;
    const long NSIG = (long)T_STEPS * BATCH * FEAT;
    const long NH   = (long)BATCH * HID;
    const long TOT = NW1 + NW2 + 2L * NG + NSIG + 6L * NH;
    for (long i = blockIdx.x * (long)blockDim.x + threadIdx.x; i < TOT;
         i += (long)gridDim.x * blockDim.x) {
        if (i < NW1) {
            long n = i / K1, k = i % K1;
            int o = orig_row(n);
            float v = (k < FEAT) ? Wih1[(long)o * FEAT + k]
                                 : Whh1[(long)o * HID + (k - FEAT)];
            g_Wp1h[i] = __float2half_rn(v);
        } else if (i < NW1 + NW2) {
            long j = i - NW1;
            long n = j / K2, k = j % K2;
            int o = orig_row(n);
            float v = (k < HID) ? Wih2[(long)o * HID + k]
                                : Whh2[(long)o * HID + (k - HID)];
            g_Wp2h[j] = __float2half_rn(v);
        } else if (i < NW1 + NW2 + NG) {
            long n = i - NW1 - NW2;
            int o = orig_row(n);
            g_b1[n] = bih1[o] + bhh1[o];
        } else if (i < NW1 + NW2 + 2L * NG) {
            long n = i - NW1 - NW2 - NG;
            int o = orig_row(n);
            g_b2[n] = bih2[o] + bhh2[o];
        } else if (i < NW1 + NW2 + 2L * NG + NSIG) {
            long j = i - NW1 - NW2 - 2L * NG;
            g_sigh[j] = __float2half_rn(signal[j]);
        } else {
            long j = i - (NW1 + NW2 + 2L * NG + NSIG);
            long seg = j / NH, o = j % NH;
            if      (seg == 0) g_h1[0][o] = __float2half_rn(0.f);
            else if (seg == 1) g_h1[1][o] = __float2half_rn(0.f);
            else if (seg == 2) g_h2[0][o] = __float2half_rn(0.f);
            else if (seg == 3) g_h2[1][o] = __float2half_rn(0.f);
            else if (seg == 4) g_c1[o]    = 0.f;
            else               g_c2[o]    = 0.f;
        }
    }
    if (blockIdx.x == 0 && threadIdx.x < 4) {
        g_bar4[threadIdx.x] = 0u;
        g_gen4[threadIdx.x] = 0u;
    }
}

// --------------------- per-M-group barrier (32 CTAs) -------------------------
__device__ __forceinline__ void group_sync(int mt, unsigned target) {
    __syncthreads();
    if (threadIdx.x == 0) {
        __threadfence();
        unsigned a = atomicAdd(&g_bar4[mt], 1u);
        if (a == NTGROUP - 1u) {
            atomicExch(&g_bar4[mt], 0u);
            __threadfence();
            atomicAdd(&g_gen4[mt], 1u);
        } else {
            while (ld_acq(&g_gen4[mt]) < target) { }
        }
        __threadfence();
    }
    __syncthreads();
}

// --------------------------- per-warp A staging ------------------------------
struct Src {
    const __half* a0; int lda0; int split;   // k32 sub-chunk idx < split -> a0
    const __half* a1; int lda1;              // otherwise a1
};

// issue one k32 sub-chunk (16 rows x 64B) into this warp's stage; 1 commit group
__device__ __forceinline__ void issue_sub(const Src& s, int idx, int rowA, int coff,
                                          uint32_t d0, uint32_t d1) {
    const __half* p;
    if (idx < s.split) p = s.a0 + (size_t)rowA * s.lda0 + idx * 32 + coff;
    else               p = s.a1 + (size_t)rowA * s.lda1 + (idx - s.split) * 32 + coff;
    cp16(d0, p);
    cp16(d1, p + 8);
    CPA_COMMIT();
}

// ---------------------- sub-chunk MMA (B resident in smem) -------------------
__device__ __forceinline__ void mma_sub(uint32_t stg, const uint32_t a_off[2],
                                        uint32_t wphase, int k16g,
                                        const uint32_t bo_sw[4][4], float acc[8][4]) {
    #pragma unroll
    for (int kk = 0; kk < 2; kk++) {
        unsigned a0, a1, a2, a3;
        LDSM4(a0, a1, a2, a3, stg + a_off[kk]);
        const int kg = k16g + kk;
        const uint32_t wblk = wphase + (uint32_t)(kg >> 2) * 8192u;
        const int k4 = kg & 3;
        unsigned b[4][4];
        #pragma unroll
        for (int p = 0; p < 4; p++)
            LDSM4(b[p][0], b[p][1], b[p][2], b[p][3], wblk + bo_sw[p][k4]);
        #pragma unroll
        for (int ni = 0; ni < 8; ni++) {
            const int p = ni >> 1, hi = (ni & 1) * 2;
            asm volatile(
                "mma.sync.aligned.m16n8k16.row.col.f32.f16.f16.f32 "
                "{%0,%1,%2,%3}, {%4,%5,%6,%7}, {%8,%9}, {%0,%1,%2,%3};\n"
                : "+f"(acc[ni][0]), "+f"(acc[ni][1]),
                  "+f"(acc[ni][2]), "+f"(acc[ni][3])
                : "r"(a0), "r"(a1), "r"(a2), "r"(a3),
                  "r"(b[p][hi]), "r"(b[p][hi + 1]));
        }
    }
}

__device__ __forceinline__ void zero_acc(float acc[8][4]) {
    #pragma unroll
    for (int ni = 0; ni < 8; ni++)
        #pragma unroll
        for (int r = 0; r < 4; r++) acc[ni][r] = 0.f;
}

// ------------------- register-local LSTM epilogue ----------------------------
__device__ __forceinline__ void epilogue(const float acc[8][4],
                                         const float br[4][2][2],
                                         float* __restrict__ cbuf,
                                         __half* __restrict__ hout,
                                         int m0, int H0, int w, int lane) {
    const int r0 = m0 + w * 16 + (lane >> 2);
    #pragma unroll
    for (int rp = 0; rp < 2; rp++) {
        const int row = r0 + rp * 8;
        #pragma unroll
        for (int j = 0; j < 2; j++) {
            const int colb = H0 + j * 8 + 2 * (lane & 3);
            float2 c2 = *(float2*)(cbuf + (size_t)row * HID + colb);
            float hv[2];
            #pragma unroll
            for (int b = 0; b < 2; b++) {
                const int rg = rp * 2 + b;
                float gi = acc[0 + j][rg] + br[0][j][b];
                float gf = acc[2 + j][rg] + br[1][j][b];
                float gg = acc[4 + j][rg] + br[2][j][b];
                float go = acc[6 + j][rg] + br[3][j][b];
                float c  = b ? c2.y : c2.x;
                float cn = sigm(gf) * c + sigm(gi) * tanhf(gg);
                if (b) c2.y = cn; else c2.x = cn;
                hv[b] = sigm(go) * tanhf(cn);
            }
            *(float2*)(cbuf + (size_t)row * HID + colb) = c2;
            *(__half2*)(hout + (size_t)row * HID + colb) =
                __floats2half2_rn(hv[0], hv[1]);
        }
    }
}

// ----------------------------- output projection -----------------------------
__device__ __forceinline__ void out_calc(int tp, const __half* __restrict__ h2cur,
                                         const float* __restrict__ Wlin,
                                         const float* __restrict__ blin,
                                         float* __restrict__ out, int ct) {
    const int tid = threadIdx.x, lane = tid & 31, wid = tid >> 5;
    if (wid >= 4) return;
    const int b = ct * 4 + wid;
    const __half* hrow = h2cur + (size_t)b * HID;
    float s0 = 0.f, s1 = 0.f;
    #pragma unroll 8
    for (int k = lane; k < HID; k += 32) {
        float hv = __half2float(__ldcg(hrow + k));
        s0 += hv * __ldg(Wlin + k);
        s1 += hv * __ldg(Wlin + HID + k);
    }
    #pragma unroll
    for (int o = 16; o; o >>= 1) {
        s0 += __shfl_xor_sync(0xffffffffu, s0, o);
        s1 += __shfl_xor_sync(0xffffffffu, s1, o);
    }
    if (lane == 0) {
        out[(size_t)b * (T_STEPS * TAGS) + tp * TAGS + 0] = s0 + blin[0];
        out[(size_t)b * (T_STEPS * TAGS) + tp * TAGS + 1] = s1 + blin[1];
    }
}

// ------------------------------ persistent kernel ----------------------------
__global__ void __launch_bounds__(NTHREADS, 1)
lstm_persistent(const float* __restrict__ Wlin, const float* __restrict__ blin,
                float* __restrict__ out) {
    extern __shared__ char smc[];
    const uint32_t smu = (uint32_t)__cvta_generic_to_shared(smc);
    const int tid = threadIdx.x, w = tid >> 5, lane = tid & 31;
    const int ct = blockIdx.x;
    const int mt = ct >> 5, nt = ct & 31;    // 4 M-groups x 32 N-tiles
    const int m0 = mt * MT, n0 = nt * NT, H0 = nt * 16;

    // ---- preload resident W1 (10 blocks) + W2 (16 blocks) into smem ----
    {
        int row = tid >> 2, part = tid & 3;
        uint32_t rb = (uint32_t)(row * 128 + part * 32);
        uint32_t o0 = rb;        o0 ^= (o0 >> 3) & 0x70u;
        uint32_t o1 = rb + 16;   o1 ^= (o1 >> 3) & 0x70u;
        const __half* s1 = g_Wp1h + (size_t)(n0 + row) * K1 + part * 16;
        for (int ckk = 0; ckk < W1_BLKS; ckk++) {
            cp16(smu + SM_W1 + ckk * 8192 + o0, s1 + ckk * 64);
            cp16(smu + SM_W1 + ckk * 8192 + o1, s1 + ckk * 64 + 8);
        }
        const __half* s2 = g_Wp2h + (size_t)(n0 + row) * K2 + part * 16;
        for (int ckk = 0; ckk < W2_BLKS; ckk++) {
            cp16(smu + SM_W2 + ckk * 8192 + o0, s2 + ckk * 64);
            cp16(smu + SM_W2 + ckk * 8192 + o1, s2 + ckk * 64 + 8);
        }
        CPA_COMMIT();
        CPA_WAIT0();
        __syncthreads();
    }

    // ---- per-thread biases in registers ----
    float b1r[4][2][2], b2r[4][2][2];
    #pragma unroll
    for (int g = 0; g < 4; g++)
        #pragma unroll
        for (int j = 0; j < 2; j++)
            #pragma unroll
            for (int b = 0; b < 2; b++) {
                int c = n0 + g * 16 + j * 8 + 2 * (lane & 3) + b;
                b1r[g][j][b] = g_b1[c];
                b2r[g][j][b] = g_b2[c];
            }

    // ---- precomputed swizzled LDSM offsets for B (n16-block p, k16-in-block) ----
    const uint32_t b_off0 = (uint32_t)(((((lane >> 4) & 1) * 8 + (lane & 7)) * 128)
                                       + ((lane >> 3) & 1) * 16);
    uint32_t bo_sw[4][4];
    #pragma unroll
    for (int p = 0; p < 4; p++)
        #pragma unroll
        for (int kk = 0; kk < 4; kk++) {
            uint32_t bo = b_off0 + (uint32_t)(p * 2048 + kk * 32);
            bo ^= (bo >> 3) & 0x70u;
            bo_sw[p][kk] = bo;
        }

    // ---- per-warp A stage: 2 slots x 1KB; 2 rows packed per 128B line -------
    const uint32_t awbase = smu + SM_AST + (uint32_t)w * 2048u;
    const uint32_t wpre = (uint32_t)((lane >> 2) * 128 + ((lane >> 1) & 1) * 64
                                     + (lane & 1) * 32);
    const uint32_t wsw  = ((uint32_t)(lane >> 2) & 7u) << 4;
    const uint32_t wd0  = wpre ^ wsw;
    const uint32_t wd1  = (wpre + 16) ^ wsw;
    const int coff = (lane & 1) * 16;                 // halves
    const int rowA = m0 + w * 16 + (lane >> 1);
    const int rr = lane & 15;
    const uint32_t apre = (uint32_t)((rr >> 1) * 128 + (rr & 1) * 64 + (lane >> 4) * 16);
    const uint32_t asw  = ((uint32_t)(rr >> 1) & 7u) << 4;
    const uint32_t a_off[2] = { apre ^ asw, (apre + 32) ^ asw };

    float acc[8][4];
    unsigned round = 0;

    // ---------------- prologue: A(0) -> h1_0 in g_h1[1] ----------------------
    {
        Src sa;
        sa.a0 = g_sigh;  sa.lda0 = FEAT; sa.split = 4;
        sa.a1 = g_h1[0]; sa.lda1 = HID;           // zeros
        issue_sub(sa, 0, rowA, coff, awbase + wd0, awbase + wd1);
        issue_sub(sa, 1, rowA, coff, awbase + 1024 + wd0, awbase + 1024 + wd1);
        zero_acc(acc);
        #pragma unroll 2
        for (int j = 0; j < 20; j++) {
            if (j + 1 < 20) CPA_WAIT1(); else CPA_WAIT0();
            __syncwarp();
            const uint32_t stg = awbase + (uint32_t)(j & 1) * 1024u;
            mma_sub(stg, a_off, smu + SM_W1, j * 2, bo_sw, acc);
            if (j + 2 < 20) issue_sub(sa, j + 2, rowA, coff, stg + wd0, stg + wd1);
        }
        epilogue(acc, b1r, g_c1, g_h1[1], m0, H0, w, lane);
        group_sync(mt, ++round);
    }

    // ------------- steady state: region_t = [ B(t) ; A(t+1) ] ----------------
    for (int t = 0; t < T_STEPS; t++) {
        const int cur = (t + 1) & 1, prev = t & 1;
        Src sb;                               // B(t): [h1_t , h2_{t-1}]
        sb.a0 = g_h1[cur]; sb.lda0 = HID; sb.split = 16;
        sb.a1 = g_h2[prev]; sb.lda1 = HID;
        Src sa;                               // A(t+1): [x_{t+1} , h1_t]
        sa.a0 = g_sigh + (size_t)((t + 1) & (T_STEPS - 1)) * BATCH * FEAT;
        sa.lda0 = FEAT; sa.split = 4;
        sa.a1 = g_h1[cur]; sa.lda1 = HID;
        const bool doA = (t + 1 < T_STEPS);

        // kick off pipeline, overlap cold start with out projection
        issue_sub(sb, 0, rowA, coff, awbase + wd0, awbase + wd1);
        issue_sub(sb, 1, rowA, coff, awbase + 1024 + wd0, awbase + 1024 + wd1);
        if (t > 0) out_calc(t - 1, g_h2[prev], Wlin, blin, out, ct);

        // ---- B(t): 32 k32 chunks; tail issues A(t+1) chunks 0,1 ----
        zero_acc(acc);
        #pragma unroll 2
        for (int j = 0; j < 32; j++) {
            CPA_WAIT1();
            __syncwarp();
            const uint32_t stg = awbase + (uint32_t)(j & 1) * 1024u;
            mma_sub(stg, a_off, smu + SM_W2, j * 2, bo_sw, acc);
            if (j + 2 < 32)
                issue_sub(sb, j + 2, rowA, coff, stg + wd0, stg + wd1);
            else if (doA)
                issue_sub(sa, j - 30, rowA, coff, stg + wd0, stg + wd1);
            else
                CPA_COMMIT();
        }
        epilogue(acc, b2r, g_c2, g_h2[cur], m0, H0, w, lane);

        // ---- A(t+1): 20 k32 chunks (pipeline already primed) ----
        if (doA) {
            zero_acc(acc);
            #pragma unroll 2
            for (int j = 0; j < 20; j++) {
                if (j + 1 < 20) CPA_WAIT1(); else CPA_WAIT0();
                __syncwarp();
                const uint32_t stg = awbase + (uint32_t)(j & 1) * 1024u;
                mma_sub(stg, a_off, smu + SM_W1, j * 2, bo_sw, acc);
                if (j + 2 < 20)
                    issue_sub(sa, j + 2, rowA, coff, stg + wd0, stg + wd1);
            }
            epilogue(acc, b1r, g_c1, g_h1[prev], m0, H0, w, lane);  // h1_{t+1}
        }
        group_sync(mt, ++round);
    }
    out_calc(T_STEPS - 1, g_h2[0], Wlin, blin, out, ct);
}

// --------------------------------- launcher ----------------------------------
extern "C" void kernel_launch(void* const* d_in, const int* in_sizes, int n_in,
                              void* d_out, int out_size) {
    const float* signal = (const float*)d_in[0];
    const float* Wih1   = (const float*)d_in[1];
    const float* Whh1   = (const float*)d_in[2];
    const float* bih1   = (const float*)d_in[3];
    const float* bhh1   = (const float*)d_in[4];
    const float* Wih2   = (const float*)d_in[5];
    const float* Whh2   = (const float*)d_in[6];
    const float* bih2   = (const float*)d_in[7];
    const float* bhh2   = (const float*)d_in[8];
    const float* Wlin   = (const float*)d_in[9];
    const float* blin   = (const float*)d_in[10];
    float* out = (float*)d_out;

    (void)in_sizes; (void)n_in; (void)out_size;

    cudaFuncSetAttribute(lstm_persistent,
                         cudaFuncAttributeMaxDynamicSharedMemorySize, SMEM_BYTES);

    prep_kernel<<<4096, 256>>>(signal, Wih1, Whh1, bih1, bhh1,
                               Wih2, Whh2, bih2, bhh2);
    lstm_persistent<<<NCTA, NTHREADS, SMEM_BYTES>>>(Wlin, blin, out);
}

// round 12
// speedup vs baseline: 1.5110x; 1.0584x over previous
#include <cuda_runtime.h>
#include <cuda_fp16.h>
#include <cstdint>

#define T_STEPS 512
#define BATCH   512
#define FEAT    128
#define HID     512
#define TAGS    2
#define NG      2048          // 4*HID
#define K1      640           // FEAT + HID
#define K2      1024          // HID + HID
#define NCTA    128
#define MT      128
#define NT      64
#define NTHREADS 256          // 8 warps: 4 M-subgroups x 2 N-halves, tile 32x32
#define NTGROUP 32            // CTAs per M-group

// resident weights: per k64 block = 64 rows(N) x 128B = 8192 B
#define W1_BLKS 10
#define W2_BLKS 16
#define SM_W1   0
#define SM_W2   (W1_BLKS * 8192)                  // 81920
#define SM_AST  ((W1_BLKS + W2_BLKS) * 8192)      // 212992: pair A stages
#define SMEM_BYTES (SM_AST + 4 * 4096)            // 229376 (224KB)

// ------------------------- device globals (scratch) -------------------------
__device__ __half g_Wp1h[NG * K1];       // permuted [n][k], fp16
__device__ __half g_Wp2h[NG * K2];
__device__ float  g_b1[NG];
__device__ float  g_b2[NG];
__device__ __half g_sigh[T_STEPS * BATCH * FEAT];
__device__ __half g_h1[2][BATCH * HID];
__device__ __half g_h2[2][BATCH * HID];
__device__ float  g_c1[BATCH * HID];
__device__ float  g_c2[BATCH * HID];
__device__ unsigned g_bar4[4];
__device__ unsigned g_gen4[4];

// ------------------------------- helpers ------------------------------------
__device__ __forceinline__ float sigm(float x) { return 1.0f / (1.0f + __expf(-x)); }
__device__ __forceinline__ void cp16(uint32_t dst, const void* src) {
    asm volatile("cp.async.cg.shared.global [%0], [%1], 16;\n" :: "r"(dst), "l"(src));
}
#define CPA_COMMIT() asm volatile("cp.async.commit_group;\n")
#define CPA_WAIT1()  asm volatile("cp.async.wait_group 1;\n")
#define CPA_WAIT0()  asm volatile("cp.async.wait_group 0;\n")
#define PBAR(mg)     asm volatile("bar.sync %0, 64;" :: "r"(1 + (mg)) : "memory")
#define LDSM4(r0, r1, r2, r3, addr)                                            \
    asm volatile("ldmatrix.sync.aligned.m8n8.x4.shared.b16 {%0,%1,%2,%3}, [%4];" \
        : "=r"(r0), "=r"(r1), "=r"(r2), "=r"(r3) : "r"(addr))

__device__ __forceinline__ unsigned ld_acq(const unsigned* p) {
    unsigned v;
    asm volatile("ld.acquire.gpu.u32 %0, [%1];" : "=r"(v) : "l"(p) : "memory");
    return v;
}

// permuted column index n -> original gate row (gate-interleave of 8)
__device__ __forceinline__ int orig_row(long n) {
    int chunk = (int)(n >> 5), w = (int)(n & 31);
    int q = w >> 3, r = w & 7;
    return q * HID + chunk * 8 + r;
}

// ------------------------------ prep kernel ---------------------------------
__global__ void prep_kernel(const float* __restrict__ signal,
                            const float* __restrict__ Wih1, const float* __restrict__ Whh1,
                            const float* __restrict__ bih1, const float* __restrict__ bhh1,
                            const float* __restrict__ Wih2, const float* __restrict__ Whh2,
                            const float* __restrict__ bih2, const float* __restrict__ bhh2) {
    const long NW1 = (long)NG * K1;
    const long NW2 = (long)NG * K2;
    const long NSIG = (long)T_STEPS * BATCH * FEAT;
    const long NH   = (long)BATCH * HID;
    const long TOT = NW1 + NW2 + 2L * NG + NSIG + 6L * NH;
    for (long i = blockIdx.x * (long)blockDim.x + threadIdx.x; i < TOT;
         i += (long)gridDim.x * blockDim.x) {
        if (i < NW1) {
            long n = i / K1, k = i % K1;
            int o = orig_row(n);
            float v = (k < FEAT) ? Wih1[(long)o * FEAT + k]
                                 : Whh1[(long)o * HID + (k - FEAT)];
            g_Wp1h[i] = __float2half_rn(v);
        } else if (i < NW1 + NW2) {
            long j = i - NW1;
            long n = j / K2, k = j % K2;
            int o = orig_row(n);
            float v = (k < HID) ? Wih2[(long)o * HID + k]
                                : Whh2[(long)o * HID + (k - HID)];
            g_Wp2h[j] = __float2half_rn(v);
        } else if (i < NW1 + NW2 + NG) {
            long n = i - NW1 - NW2;
            int o = orig_row(n);
            g_b1[n] = bih1[o] + bhh1[o];
        } else if (i < NW1 + NW2 + 2L * NG) {
            long n = i - NW1 - NW2 - NG;
            int o = orig_row(n);
            g_b2[n] = bih2[o] + bhh2[o];
        } else if (i < NW1 + NW2 + 2L * NG + NSIG) {
            long j = i - NW1 - NW2 - 2L * NG;
            g_sigh[j] = __float2half_rn(signal[j]);
        } else {
            long j = i - (NW1 + NW2 + 2L * NG + NSIG);
            long seg = j / NH, o = j % NH;
            if      (seg == 0) g_h1[0][o] = __float2half_rn(0.f);
            else if (seg == 1) g_h1[1][o] = __float2half_rn(0.f);
            else if (seg == 2) g_h2[0][o] = __float2half_rn(0.f);
            else if (seg == 3) g_h2[1][o] = __float2half_rn(0.f);
            else if (seg == 4) g_c1[o]    = 0.f;
            else               g_c2[o]    = 0.f;
        }
    }
    if (blockIdx.x == 0 && threadIdx.x < 4) {
        g_bar4[threadIdx.x] = 0u;
        g_gen4[threadIdx.x] = 0u;
    }
}

// --------------------- per-M-group barrier (32 CTAs) -------------------------
__device__ __forceinline__ void group_sync(int mt, unsigned target) {
    __syncthreads();
    if (threadIdx.x == 0) {
        __threadfence();
        unsigned a = atomicAdd(&g_bar4[mt], 1u);
        if (a == NTGROUP - 1u) {
            atomicExch(&g_bar4[mt], 0u);
            __threadfence();
            atomicAdd(&g_gen4[mt], 1u);
        } else {
            while (ld_acq(&g_gen4[mt]) < target) { }
        }
        __threadfence();
    }
    __syncthreads();
}

// --------------------------- pair A staging ----------------------------------
struct Src {
    const __half* a0; int lda0; int split;   // k32 sub-chunk idx < split -> a0
    const __half* a1; int lda1;              // otherwise a1
};

// each warp loads its half (16 rows x 32B/lane) of the pair's 32-row stage
__device__ __forceinline__ void issue_sub(const Src& s, int idx, int rowA, int coff,
                                          uint32_t d0, uint32_t d1) {
    const __half* p;
    if (idx < s.split) p = s.a0 + (size_t)rowA * s.lda0 + idx * 32 + coff;
    else               p = s.a1 + (size_t)rowA * s.lda1 + (idx - s.split) * 32 + coff;
    cp16(d0, p);
    cp16(d1, p + 8);
    CPA_COMMIT();
}

// ------------------------ fragment load / MMA --------------------------------
struct Frags { unsigned a[2][2][4]; unsigned b[2][2][4]; };  // [kk][mi/p2][4]

__device__ __forceinline__ void load_frags(Frags& f, uint32_t stg,
                                           const uint32_t a_off[2][2],
                                           uint32_t wphase, int k16g,
                                           const uint32_t bo_sw[2][4]) {
    #pragma unroll
    for (int kk = 0; kk < 2; kk++) {
        #pragma unroll
        for (int mi = 0; mi < 2; mi++)
            LDSM4(f.a[kk][mi][0], f.a[kk][mi][1], f.a[kk][mi][2], f.a[kk][mi][3],
                  stg + a_off[mi][kk]);
        const int kg = k16g + kk;
        const uint32_t wblk = wphase + (uint32_t)(kg >> 2) * 8192u;
        const int k4 = kg & 3;
        #pragma unroll
        for (int p2 = 0; p2 < 2; p2++)
            LDSM4(f.b[kk][p2][0], f.b[kk][p2][1], f.b[kk][p2][2], f.b[kk][p2][3],
                  wblk + bo_sw[p2][k4]);
    }
}

__device__ __forceinline__ void mma_frags(const Frags& f, float acc[2][4][4]) {
    #pragma unroll
    for (int kk = 0; kk < 2; kk++)
        #pragma unroll
        for (int mi = 0; mi < 2; mi++)
            #pragma unroll
            for (int j = 0; j < 4; j++) {
                const int p2 = j >> 1, hi = (j & 1) * 2;
                asm volatile(
                    "mma.sync.aligned.m16n8k16.row.col.f32.f16.f16.f32 "
                    "{%0,%1,%2,%3}, {%4,%5,%6,%7}, {%8,%9}, {%0,%1,%2,%3};\n"
                    : "+f"(acc[mi][j][0]), "+f"(acc[mi][j][1]),
                      "+f"(acc[mi][j][2]), "+f"(acc[mi][j][3])
                    : "r"(f.a[kk][mi][0]), "r"(f.a[kk][mi][1]),
                      "r"(f.a[kk][mi][2]), "r"(f.a[kk][mi][3]),
                      "r"(f.b[kk][p2][hi]), "r"(f.b[kk][p2][hi + 1]));
            }
}

__device__ __forceinline__ void zero_acc(float acc[2][4][4]) {
    #pragma unroll
    for (int mi = 0; mi < 2; mi++)
        #pragma unroll
        for (int j = 0; j < 4; j++)
            #pragma unroll
            for (int r = 0; r < 4; r++) acc[mi][j][r] = 0.f;
}

// ------------------- register-local LSTM epilogue ----------------------------
// warp (mg,nh): rows m0+mg*32+[0..31], h-cols H0+nh*8+[0..7], all 4 gates
__device__ __forceinline__ void epilogue(const float acc[2][4][4],
                                         const float br[4][2],
                                         float* __restrict__ cbuf,
                                         __half* __restrict__ hout,
                                         int base_row, int colb, int lane) {
    #pragma unroll
    for (int mi = 0; mi < 2; mi++) {
        #pragma unroll
        for (int rp = 0; rp < 2; rp++) {
            const int row = base_row + mi * 16 + rp * 8;
            float2 c2 = *(float2*)(cbuf + (size_t)row * HID + colb);
            float hv[2];
            #pragma unroll
            for (int b = 0; b < 2; b++) {
                const int rg = rp * 2 + b;
                float gi = acc[mi][0][rg] + br[0][b];
                float gf = acc[mi][1][rg] + br[1][b];
                float gg = acc[mi][2][rg] + br[2][b];
                float go = acc[mi][3][rg] + br[3][b];
                float c  = b ? c2.y : c2.x;
                float cn = sigm(gf) * c + sigm(gi) * tanhf(gg);
                if (b) c2.y = cn; else c2.x = cn;
                hv[b] = sigm(go) * tanhf(cn);
            }
            *(float2*)(cbuf + (size_t)row * HID + colb) = c2;
            *(__half2*)(hout + (size_t)row * HID + colb) =
                __floats2half2_rn(hv[0], hv[1]);
        }
    }
}

// ----------------------------- output projection -----------------------------
__device__ __forceinline__ void out_calc(int tp, const __half* __restrict__ h2cur,
                                         const float* __restrict__ Wlin,
                                         const float* __restrict__ blin,
                                         float* __restrict__ out, int ct) {
    const int tid = threadIdx.x, lane = tid & 31, wid = tid >> 5;
    if (wid >= 4) return;
    const int b = ct * 4 + wid;
    const __half* hrow = h2cur + (size_t)b * HID;
    float s0 = 0.f, s1 = 0.f;
    #pragma unroll 8
    for (int k = lane; k < HID; k += 32) {
        float hv = __half2float(__ldcg(hrow + k));
        s0 += hv * __ldg(Wlin + k);
        s1 += hv * __ldg(Wlin + HID + k);
    }
    #pragma unroll
    for (int o = 16; o; o >>= 1) {
        s0 += __shfl_xor_sync(0xffffffffu, s0, o);
        s1 += __shfl_xor_sync(0xffffffffu, s1, o);
    }
    if (lane == 0) {
        out[(size_t)b * (T_STEPS * TAGS) + tp * TAGS + 0] = s0 + blin[0];
        out[(size_t)b * (T_STEPS * TAGS) + tp * TAGS + 1] = s1 + blin[1];
    }
}

// ------------------------------ persistent kernel ----------------------------
__global__ void __launch_bounds__(NTHREADS, 1)
lstm_persistent(const float* __restrict__ Wlin, const float* __restrict__ blin,
                float* __restrict__ out) {
    extern __shared__ char smc[];
    const uint32_t smu = (uint32_t)__cvta_generic_to_shared(smc);
    const int tid = threadIdx.x, w = tid >> 5, lane = tid & 31;
    const int mg = w >> 1, nh = w & 1;       // M-subgroup / N-half
    const int ct = blockIdx.x;
    const int mt = ct >> 5, nt = ct & 31;    // 4 M-groups x 32 N-tiles
    const int m0 = mt * MT, n0 = nt * NT, H0 = nt * 16;

    // ---- preload resident W1 (10 blocks) + W2 (16 blocks) into smem ----
    {
        int row = tid >> 2, part = tid & 3;
        uint32_t rb = (uint32_t)(row * 128 + part * 32);
        uint32_t o0 = rb;        o0 ^= (o0 >> 3) & 0x70u;
        uint32_t o1 = rb + 16;   o1 ^= (o1 >> 3) & 0x70u;
        const __half* s1 = g_Wp1h + (size_t)(n0 + row) * K1 + part * 16;
        for (int ckk = 0; ckk < W1_BLKS; ckk++) {
            cp16(smu + SM_W1 + ckk * 8192 + o0, s1 + ckk * 64);
            cp16(smu + SM_W1 + ckk * 8192 + o1, s1 + ckk * 64 + 8);
        }
        const __half* s2 = g_Wp2h + (size_t)(n0 + row) * K2 + part * 16;
        for (int ckk = 0; ckk < W2_BLKS; ckk++) {
            cp16(smu + SM_W2 + ckk * 8192 + o0, s2 + ckk * 64);
            cp16(smu + SM_W2 + ckk * 8192 + o1, s2 + ckk * 64 + 8);
        }
        CPA_COMMIT();
        CPA_WAIT0();
        __syncthreads();
    }

    // ---- per-thread biases in registers (gate j, sub-col b) ----
    float b1r[4][2], b2r[4][2];
    #pragma unroll
    for (int g = 0; g < 4; g++)
        #pragma unroll
        for (int b = 0; b < 2; b++) {
            int c = n0 + nh * 32 + g * 8 + 2 * (lane & 3) + b;
            b1r[g][b] = g_b1[c];
            b2r[g][b] = g_b2[c];
        }

    // ---- swizzled LDSM offsets for B: this warp's two n16 blocks ----
    const uint32_t b_off0 = (uint32_t)(((((lane >> 4) & 1) * 8 + (lane & 7)) * 128)
                                       + ((lane >> 3) & 1) * 16);
    uint32_t bo_sw[2][4];
    #pragma unroll
    for (int p2 = 0; p2 < 2; p2++)
        #pragma unroll
        for (int kk = 0; kk < 4; kk++) {
            uint32_t bo = b_off0 + (uint32_t)((2 * nh + p2) * 2048 + kk * 32);
            bo ^= (bo >> 3) & 0x70u;
            bo_sw[p2][kk] = bo;
        }

    // ---- pair A stage: 2 slots x 2KB (32 rows, 2 rows per 128B line) ----
    const uint32_t pstage = smu + SM_AST + (uint32_t)mg * 4096u;
    const int pt = nh * 32 + lane;                       // pair-local thread
    const uint32_t wpre = (uint32_t)((pt >> 2) * 128 + ((pt >> 1) & 1) * 64
                                     + (pt & 1) * 32);
    const uint32_t wsw  = ((uint32_t)(pt >> 2) & 7u) << 4;
    const uint32_t wd0  = wpre ^ wsw;
    const uint32_t wd1  = (wpre + 16) ^ wsw;
    const int coff = (lane & 1) * 16;                    // halves
    const int rowA = m0 + mg * 32 + nh * 16 + (lane >> 1);

    // ---- LDSM A read offsets [mi][kk] ----
    const int rr = lane & 15;
    uint32_t a_off[2][2];
    #pragma unroll
    for (int mi = 0; mi < 2; mi++)
        #pragma unroll
        for (int kk = 0; kk < 2; kk++) {
            uint32_t ap = (uint32_t)(mi * 1024 + (rr >> 1) * 128 + (rr & 1) * 64
                                     + kk * 32 + (lane >> 4) * 16);
            ap ^= ((uint32_t)(rr >> 1) & 7u) << 4;
            a_off[mi][kk] = ap;
        }

    const int base_row = m0 + mg * 32 + (lane >> 2);
    const int colb = H0 + nh * 8 + 2 * (lane & 3);

    float acc[2][4][4];
    Frags f;
    unsigned round = 0;

    // ---------------- prologue: A(0) -> h1_0 in g_h1[1] ----------------------
    {
        Src sa;
        sa.a0 = g_sigh;  sa.lda0 = FEAT; sa.split = 4;
        sa.a1 = g_h1[0]; sa.lda1 = HID;           // zeros
        issue_sub(sa, 0, rowA, coff, pstage + wd0, pstage + wd1);
        issue_sub(sa, 1, rowA, coff, pstage + 2048 + wd0, pstage + 2048 + wd1);
        zero_acc(acc);
        #pragma unroll 2
        for (int j = 0; j < 20; j++) {
            if (j + 1 < 20) CPA_WAIT1(); else CPA_WAIT0();
            PBAR(mg);
            const uint32_t stg = pstage + (uint32_t)(j & 1) * 2048u;
            load_frags(f, stg, a_off, smu + SM_W1, j * 2, bo_sw);
            if (j + 2 < 20) issue_sub(sa, j + 2, rowA, coff, stg + wd0, stg + wd1);
            mma_frags(f, acc);
        }
        epilogue(acc, b1r, g_c1, g_h1[1], base_row, colb, lane);
        group_sync(mt, ++round);
    }

    // ------------- steady state: region_t = [ B(t) ; A(t+1) ] ----------------
    for (int t = 0; t < T_STEPS; t++) {
        const int cur = (t + 1) & 1, prev = t & 1;
        Src sb;                               // B(t): [h1_t , h2_{t-1}]
        sb.a0 = g_h1[cur]; sb.lda0 = HID; sb.split = 16;
        sb.a1 = g_h2[prev]; sb.lda1 = HID;
        Src sa;                               // A(t+1): [x_{t+1} , h1_t]
        sa.a0 = g_sigh + (size_t)((t + 1) & (T_STEPS - 1)) * BATCH * FEAT;
        sa.lda0 = FEAT; sa.split = 4;
        sa.a1 = g_h1[cur]; sa.lda1 = HID;
        const bool doA = (t + 1 < T_STEPS);

        // kick off pipeline, overlap cold start with out projection
        issue_sub(sb, 0, rowA, coff, pstage + wd0, pstage + wd1);
        issue_sub(sb, 1, rowA, coff, pstage + 2048 + wd0, pstage + 2048 + wd1);
        if (t > 0) out_calc(t - 1, g_h2[prev], Wlin, blin, out, ct);

        // ---- B(t): 32 k32 chunks; tail issues A(t+1) chunks 0,1 ----
        zero_acc(acc);
        #pragma unroll 2
        for (int j = 0; j < 32; j++) {
            CPA_WAIT1();
            PBAR(mg);
            const uint32_t stg = pstage + (uint32_t)(j & 1) * 2048u;
            load_frags(f, stg, a_off, smu + SM_W2, j * 2, bo_sw);
            if (j + 2 < 32)
                issue_sub(sb, j + 2, rowA, coff, stg + wd0, stg + wd1);
            else if (doA)
                issue_sub(sa, j - 30, rowA, coff, stg + wd0, stg + wd1);
            else
                CPA_COMMIT();
            mma_frags(f, acc);
        }
        epilogue(acc, b2r, g_c2, g_h2[cur], base_row, colb, lane);

        // ---- A(t+1): 20 k32 chunks (pipeline already primed) ----
        if (doA) {
            zero_acc(acc);
            #pragma unroll 2
            for (int j = 0; j < 20; j++) {
                if (j + 1 < 20) CPA_WAIT1(); else CPA_WAIT0();
                PBAR(mg);
                const uint32_t stg = pstage + (uint32_t)(j & 1) * 2048u;
                load_frags(f, stg, a_off, smu + SM_W1, j * 2, bo_sw);
                if (j + 2 < 20)
                    issue_sub(sa, j + 2, rowA, coff, stg + wd0, stg + wd1);
                mma_frags(f, acc);
            }
            epilogue(acc, b1r, g_c1, g_h1[prev], base_row, colb, lane);  // h1_{t+1}
        }
        group_sync(mt, ++round);
    }
    out_calc(T_STEPS - 1, g_h2[0], Wlin, blin, out, ct);
}

// --------------------------------- launcher ----------------------------------
extern "C" void kernel_launch(void* const* d_in, const int* in_sizes, int n_in,
                              void* d_out, int out_size) {
    const float* signal = (const float*)d_in[0];
    const float* Wih1   = (const float*)d_in[1];
    const float* Whh1   = (const float*)d_in[2];
    const float* bih1   = (const float*)d_in[3];
    const float* bhh1   = (const float*)d_in[4];
    const float* Wih2   = (const float*)d_in[5];
    const float* Whh2   = (const float*)d_in[6];
    const float* bih2   = (const float*)d_in[7];
    const float* bhh2   = (const float*)d_in[8];
    const float* Wlin   = (const float*)d_in[9];
    const float* blin   = (const float*)d_in[10];
    float* out = (float*)d_out;

    (void)in_sizes; (void)n_in; (void)out_size;

    cudaFuncSetAttribute(lstm_persistent,
                         cudaFuncAttributeMaxDynamicSharedMemorySize, SMEM_BYTES);

    prep_kernel<<<4096, 256>>>(signal, Wih1, Whh1, bih1, bhh1,
                               Wih2, Whh2, bih2, bhh2);
    lstm_persistent<<<NCTA, NTHREADS, SMEM_BYTES>>>(Wlin, blin, out);
}